// round 13
// baseline (speedup 1.0000x reference)
#include <cuda_runtime.h>
#include <cuda_bf16.h>
#include <cuda_fp16.h>
#include <math_constants.h>
#include <cstdint>

// Problem constants
#define NN   50000
#define EE   200000
#define RR   4
#define CC   128
#define HH   4
#define DD   32

#define LO_SCALE     2048.0f
#define INV_LO_SCALE (1.0f / 2048.0f)

// ---------------------------------------------------------------------------
// Device scratch (allocation-free rule: __device__ globals)
// ---------------------------------------------------------------------------
__device__ __half g_fsh[RR * NN * CC];   // fp16 fs
__device__ __half g_fdh[RR * NN * CC];   // fp16 fd
__device__ int    g_cnt[RR * NN];
__device__ int    g_off[RR * (NN + 1)];
__device__ int    g_src[RR * EE];
__device__ __half g_ahi[NN * CC];        // fp16 hi/lo split GEMM inputs
__device__ __half g_alo[NN * CC];        // lo pre-scaled by 2048
__device__ __half g_whi[3 * 8 * CC * CC];   // [layer][block(8)][n][k]
__device__ __half g_wlo[3 * 8 * CC * CC];
__device__ float  g_bias[3 * 8 * CC];

// ---------------------------------------------------------------------------
// CSR construction
// ---------------------------------------------------------------------------
__global__ void k_zero_cnt(int* cnt) {
    int i = blockIdx.x * blockDim.x + threadIdx.x;
    if (i < RR * NN) cnt[i] = 0;
}
__global__ void k_count(const int* __restrict__ edst, int* cnt) {
    int i = blockIdx.x * blockDim.x + threadIdx.x;
    if (i >= RR * EE) return;
    int r = i / EE;
    atomicAdd(&cnt[r * NN + edst[i]], 1);
}
// scan counts -> offsets; ALSO writes fill cursors (cnt becomes cursor array)
__global__ void k_scan(int* cnt, int* off) {
    int r = blockIdx.x;
    int t = threadIdx.x;
    const int CH = (NN + 1023) / 1024;
    __shared__ int sums[1024];
    int base = t * CH, s = 0;
    for (int i = 0; i < CH; i++) { int idx = base + i; if (idx < NN) s += cnt[r * NN + idx]; }
    sums[t] = s;
    __syncthreads();
    for (int o = 1; o < 1024; o <<= 1) {
        int v = (t >= o) ? sums[t - o] : 0;
        __syncthreads();
        sums[t] += v;
        __syncthreads();
    }
    int run = (t == 0) ? 0 : sums[t - 1];
    for (int i = 0; i < CH; i++) {
        int idx = base + i;
        if (idx < NN) {
            int c = cnt[r * NN + idx];
            off[r * (NN + 1) + idx] = run;
            cnt[r * NN + idx] = run;     // cursor for k_fill
            run += c;
        }
    }
    if (t == 1023) off[r * (NN + 1) + NN] = run;
}
__global__ void k_fill(const int* __restrict__ esrc, const int* __restrict__ edst,
                       int* cur, int* csr_src) {
    int i = blockIdx.x * blockDim.x + threadIdx.x;
    if (i >= RR * EE) return;
    int r = i / EE;
    int pos = atomicAdd(&cur[r * NN + edst[i]], 1);
    csr_src[r * EE + pos] = esrc[i];
}

// ---------------------------------------------------------------------------
// fp32 -> fp16 hi/lo split conversions (lo pre-scaled by 2048)
// ---------------------------------------------------------------------------
__device__ __forceinline__ void split_h(float v, __half& h, __half& l) {
    h = __float2half_rn(v);
    l = __float2half_rn((v - __half2float(h)) * LO_SCALE);
}

__global__ void k_cvt_x(const float* __restrict__ x,
                        __half* __restrict__ hi, __half* __restrict__ lo) {
    int i = blockIdx.x * blockDim.x + threadIdx.x;
    if (i >= NN * CC / 4) return;
    float4 v = ((const float4*)x)[i];
    __half h0, h1, h2, h3, l0, l1, l2, l3;
    split_h(v.x, h0, l0); split_h(v.y, h1, l1);
    split_h(v.z, h2, l2); split_h(v.w, h3, l3);
    ((__half2*)hi)[2 * i]     = __halves2half2(h0, h1);
    ((__half2*)hi)[2 * i + 1] = __halves2half2(h2, h3);
    ((__half2*)lo)[2 * i]     = __halves2half2(l0, l1);
    ((__half2*)lo)[2 * i + 1] = __halves2half2(l2, l3);
}

// Fused weight conversion for all 3 layers x {src,dst}
struct WParams {
    const float* W[6];    // Wsrc0, Wdst0, Wsrc1, Wdst1, Wsrc2, Wdst2
    const float* bv[6];
};
__global__ void k_cvt_w_all(WParams p,
                            __half* __restrict__ w_hi, __half* __restrict__ w_lo,
                            float* __restrict__ bias_out) {
    int i = blockIdx.x * blockDim.x + threadIdx.x;
    if (i >= 6 * RR * CC * CC) return;
    int s    = i / (RR * CC * CC);
    int rem  = i - s * (RR * CC * CC);
    int r    = rem / (CC * CC);
    int rem2 = rem - r * (CC * CC);
    int n    = rem2 / CC;
    int k    = rem2 - n * CC;
    int l = s >> 1, ty = s & 1;
    int blk = l * 8 + ty * 4 + r;
    float w = p.W[s][(size_t)r * CC * CC + (size_t)k * CC + n];
    __half h, lo;
    split_h(w, h, lo);
    size_t oidx = (size_t)blk * CC * CC + (size_t)n * CC + k;
    w_hi[oidx] = h;
    w_lo[oidx] = lo;
    if (k == 0) bias_out[blk * CC + n] = p.bv[s][r * CC + n];
}

// ---------------------------------------------------------------------------
// HMMA helpers
// ---------------------------------------------------------------------------
__device__ __forceinline__ uint32_t smem_u32(const void* p) {
    uint32_t a;
    asm("{ .reg .u64 t; cvta.to.shared.u64 t, %1; cvt.u32.u64 %0, t; }"
        : "=r"(a) : "l"(p));
    return a;
}
__device__ __forceinline__ void ldsm_x4(uint32_t* r, uint32_t addr) {
    asm volatile("ldmatrix.sync.aligned.m8n8.x4.shared.b16 {%0,%1,%2,%3}, [%4];"
        : "=r"(r[0]), "=r"(r[1]), "=r"(r[2]), "=r"(r[3]) : "r"(addr));
}
// fp16 inputs, fp32 accumulate (hi*hi term)
#define MMA16816F(c, a, b) \
    asm volatile("mma.sync.aligned.m16n8k16.row.col.f32.f16.f16.f32 " \
        "{%0,%1,%2,%3}, {%4,%5,%6,%7}, {%8,%9}, {%0,%1,%2,%3};" \
        : "+f"((c)[0]), "+f"((c)[1]), "+f"((c)[2]), "+f"((c)[3]) \
        : "r"((a)[0]), "r"((a)[1]), "r"((a)[2]), "r"((a)[3]), \
          "r"((b)[0]), "r"((b)[1]))
// fp16 inputs, fp16 accumulate (lo-correction terms; possibly double-rate)
#define MMA16816H(c, a, b) \
    asm volatile("mma.sync.aligned.m16n8k16.row.col.f16.f16.f16.f16 " \
        "{%0,%1}, {%2,%3,%4,%5}, {%6,%7}, {%0,%1};" \
        : "+r"((c)[0]), "+r"((c)[1]) \
        : "r"((a)[0]), "r"((a)[1]), "r"((a)[2]), "r"((a)[3]), \
          "r"((b)[0]), "r"((b)[1]))

__device__ __forceinline__ void cp_async16(uint32_t saddr, const void* gptr, bool pred) {
    int sz = pred ? 16 : 0;   // src-size 0 => zero-fill destination
    asm volatile("cp.async.cg.shared.global [%0], [%1], 16, %2;"
        :: "r"(saddr), "l"(gptr), "r"(sz));
}
#define CP_COMMIT() asm volatile("cp.async.commit_group;" ::: "memory")

// K chunked 2 x 64; padded row stride 72 elems -> ldmatrix conflict-free.
#define KCH3   64
#define TP3    72
#define TILE3  (128 * TP3)
#define STAGE3 (4 * TILE3)
#define GEMM_SMEM3 (2 * STAGE3 * 2)   // 147456 B

// ---------------------------------------------------------------------------
// fp16 hi/lo split GEMM via mma.sync — 512 threads, warp tile 32x32.
// C = Ahi@Bhi (fp32 acc) + (Ahi@Blo' + Alo'@Bhi) (fp16 acc, x1/2048 epilogue)
// ---------------------------------------------------------------------------
__global__ __launch_bounds__(512) void k_gemm_mma512(
    const __half* __restrict__ a_hi, const __half* __restrict__ a_lo,
    const __half* __restrict__ w_hi, const __half* __restrict__ w_lo,
    const float* __restrict__ bias,
    __half* __restrict__ fs, __half* __restrict__ fd) {
    extern __shared__ __align__(16) char dsm[];
    __half* smem = (__half*)dsm;

    const int tid  = threadIdx.x;
    const int wid  = tid >> 5;
    const int lane = tid & 31;
    const int wm   = wid >> 2;
    const int wn   = wid & 3;
    const int m0   = blockIdx.x * 128;
    const int b    = blockIdx.y;

    const __half* srcs[4] = {
        a_hi + (size_t)m0 * CC, a_lo + (size_t)m0 * CC,
        w_hi + (size_t)b * CC * CC, w_lo + (size_t)b * CC * CC };

    auto prefetch = [&](int c, int s) {
        int k0 = c * KCH3;
        __half* st = smem + s * STAGE3;
        #pragma unroll
        for (int i = 0; i < 8; i++) {
            int idx = tid + i * 512;
            int t   = idx >> 10;
            int w   = idx & 1023;
            int row = w >> 3, ch = w & 7;
            const __half* gp = srcs[t] + (size_t)row * CC + k0 + ch * 8;
            uint32_t sa = smem_u32(st + t * TILE3 + row * TP3 + ch * 8);
            bool ok = (t >= 2) || ((m0 + row) < NN);
            cp_async16(sa, gp, ok);
        }
        CP_COMMIT();
    };

    float acc[2][4][4];
    uint32_t accl[2][4][2];
    #pragma unroll
    for (int i = 0; i < 2; i++)
        #pragma unroll
        for (int j = 0; j < 4; j++) {
            #pragma unroll
            for (int q = 0; q < 4; q++) acc[i][j][q] = 0.f;
            accl[i][j][0] = 0u; accl[i][j][1] = 0u;
        }

    const int sub = lane >> 3;
    const int rin = lane & 7;

    prefetch(0, 0);
    prefetch(1, 1);

    #pragma unroll
    for (int c = 0; c < 2; c++) {
        if (c == 0) asm volatile("cp.async.wait_group 1;" ::: "memory");
        else        asm volatile("cp.async.wait_group 0;" ::: "memory");
        __syncthreads();

        __half* sAhi = smem + c * STAGE3;
        __half* sAlo = sAhi + TILE3;
        __half* sBhi = sAlo + TILE3;
        __half* sBlo = sBhi + TILE3;

        #pragma unroll
        for (int kk = 0; kk < KCH3; kk += 16) {
            uint32_t afh[2][4], afl[2][4], bfh[4][2], bfl[4][2];
            #pragma unroll
            for (int mt = 0; mt < 2; mt++) {
                int ar = wm * 32 + mt * 16 + (sub & 1) * 8 + rin;
                int ac = kk + (sub >> 1) * 8;
                int off = ar * TP3 + ac;
                ldsm_x4(afh[mt], smem_u32(sAhi + off));
                ldsm_x4(afl[mt], smem_u32(sAlo + off));
            }
            #pragma unroll
            for (int nt2 = 0; nt2 < 2; nt2++) {
                int br = wn * 32 + nt2 * 16 + (sub >> 1) * 8 + rin;
                int bc = kk + (sub & 1) * 8;
                int off = br * TP3 + bc;
                uint32_t t[4];
                ldsm_x4(t, smem_u32(sBhi + off));
                bfh[nt2 * 2][0] = t[0]; bfh[nt2 * 2][1] = t[1];
                bfh[nt2 * 2 + 1][0] = t[2]; bfh[nt2 * 2 + 1][1] = t[3];
                ldsm_x4(t, smem_u32(sBlo + off));
                bfl[nt2 * 2][0] = t[0]; bfl[nt2 * 2][1] = t[1];
                bfl[nt2 * 2 + 1][0] = t[2]; bfl[nt2 * 2 + 1][1] = t[3];
            }
            #pragma unroll
            for (int mt = 0; mt < 2; mt++)
                #pragma unroll
                for (int nt = 0; nt < 4; nt++) {
                    MMA16816F(acc[mt][nt], afh[mt], bfh[nt]);   // hi*hi fp32
                    MMA16816H(accl[mt][nt], afh[mt], bfl[nt]);  // hi*lo fp16
                    MMA16816H(accl[mt][nt], afl[mt], bfh[nt]);  // lo*hi fp16
                }
        }
    }

    __half* outp = (b < 4) ? (fs + (size_t)b * NN * CC)
                           : (fd + (size_t)(b - 4) * NN * CC);
    const float* bv = bias + b * CC;
    const int qr = lane >> 2, qc = lane & 3;
    #pragma unroll
    for (int mt = 0; mt < 2; mt++) {
        int mA = m0 + wm * 32 + mt * 16 + qr;
        #pragma unroll
        for (int nt = 0; nt < 4; nt++) {
            int n = wn * 32 + nt * 8 + qc * 2;
            float b0 = bv[n], b1 = bv[n + 1];
            float2 lo01 = __half22float2(*(__half2*)&accl[mt][nt][0]);
            float2 lo23 = __half22float2(*(__half2*)&accl[mt][nt][1]);
            if (mA < NN) {
                __half2 v0 = __floats2half2_rn(
                    acc[mt][nt][0] + lo01.x * INV_LO_SCALE + b0,
                    acc[mt][nt][1] + lo01.y * INV_LO_SCALE + b1);
                *(__half2*)(outp + (size_t)mA * CC + n) = v0;
            }
            if (mA + 8 < NN) {
                __half2 v1 = __floats2half2_rn(
                    acc[mt][nt][2] + lo23.x * INV_LO_SCALE + b0,
                    acc[mt][nt][3] + lo23.y * INV_LO_SCALE + b1);
                *(__half2*)(outp + (size_t)(mA + 8) * CC + n) = v1;
            }
        }
    }
}

// ---------------------------------------------------------------------------
// Edge aggregation v5: chunk-of-8 batch softmax.
// One warp per dst, 4 heads in 8-lane groups; per chunk: 8 independent loads
// (MLP=8), 8 independent score chains, one max/sum, ONE merge into the
// running state — removes the per-edge serial rescale chain.
// ---------------------------------------------------------------------------
__device__ __forceinline__ float4 h4_to_f4(uint2 raw) {
    __half2 a = *reinterpret_cast<__half2*>(&raw.x);
    __half2 b = *reinterpret_cast<__half2*>(&raw.y);
    float2 fa = __half22float2(a), fb = __half22float2(b);
    return make_float4(fa.x, fa.y, fb.x, fb.y);
}

template <bool MEAN>
__global__ __launch_bounds__(256) void k_edge_agg5(
    const __half* __restrict__ fs, const __half* __restrict__ fd,
    const float* __restrict__ attn,
    const int* __restrict__ off, const int* __restrict__ csr_src,
    __half* __restrict__ out_hi, __half* __restrict__ out_lo,
    float* __restrict__ out_f) {
    int dst  = (blockIdx.x * blockDim.x + threadIdx.x) >> 5;
    int lane = threadIdx.x & 31;
    if (dst >= NN) return;
    const int dbase = (lane >> 3) * DD + (lane & 7) * 4;

    float4 total = make_float4(0.f, 0.f, 0.f, 0.f);
    #pragma unroll
    for (int r = 0; r < RR; r++) {
        const __half* fsr = fs + (size_t)r * NN * CC;
        float4 fdv = h4_to_f4(*(const uint2*)(fd + (size_t)r * NN * CC
                                              + (size_t)dst * CC + dbase));
        float4 av  = *(const float4*)(attn + r * HH * DD + dbase);
        int beg = off[r * (NN + 1) + dst];
        int end = off[r * (NN + 1) + dst + 1];
        if (beg >= end) continue;
        const int* sp = csr_src + r * EE;

        float m = -CUDART_INF_F, den = 0.f;
        float4 acc = make_float4(0.f, 0.f, 0.f, 0.f);

        for (int c0 = beg; c0 < end; c0 += 8) {
            int nn_ = end - c0;                  // edges in this chunk (>=1)
            uint2 raw[8];
            #pragma unroll
            for (int j = 0; j < 8; j++) {
                raw[j] = make_uint2(0u, 0u);
                if (j < nn_)
                    raw[j] = *(const uint2*)(fsr + (size_t)sp[c0 + j] * CC + dbase);
            }
            float4 f[8];
            float p[8];
            #pragma unroll
            for (int j = 0; j < 8; j++) {
                f[j] = h4_to_f4(raw[j]);
                float x0 = f[j].x + fdv.x, x1 = f[j].y + fdv.y;
                float x2 = f[j].z + fdv.z, x3 = f[j].w + fdv.w;
                x0 = (x0 > 0.f) ? x0 : 0.2f * x0;
                x1 = (x1 > 0.f) ? x1 : 0.2f * x1;
                x2 = (x2 > 0.f) ? x2 : 0.2f * x2;
                x3 = (x3 > 0.f) ? x3 : 0.2f * x3;
                p[j] = x0 * av.x + x1 * av.y + x2 * av.z + x3 * av.w;
            }
            #pragma unroll
            for (int j = 0; j < 8; j++) {
                p[j] += __shfl_xor_sync(0xFFFFFFFFu, p[j], 1);
                p[j] += __shfl_xor_sync(0xFFFFFFFFu, p[j], 2);
                p[j] += __shfl_xor_sync(0xFFFFFFFFu, p[j], 4);
                if (j >= nn_) p[j] = -CUDART_INF_F;
            }
            // chunk max (tree)
            float m01 = fmaxf(p[0], p[1]), m23 = fmaxf(p[2], p[3]);
            float m45 = fmaxf(p[4], p[5]), m67 = fmaxf(p[6], p[7]);
            float cm = fmaxf(fmaxf(m01, m23), fmaxf(m45, m67));
            // chunk weights + sums (independent FMAs)
            float cden = 0.f;
            float4 cacc = make_float4(0.f, 0.f, 0.f, 0.f);
            #pragma unroll
            for (int j = 0; j < 8; j++) {
                float w = __expf(p[j] - cm);      // 0 for padding lanes
                cden += w;
                cacc.x += w * f[j].x;
                cacc.y += w * f[j].y;
                cacc.z += w * f[j].z;
                cacc.w += w * f[j].w;
            }
            // single merge into running state
            float nm = fmaxf(m, cm);
            float so = __expf(m - nm);            // 0 on first chunk
            float sn = __expf(cm - nm);
            m = nm;
            den = den * so + cden * sn;
            acc.x = acc.x * so + cacc.x * sn;
            acc.y = acc.y * so + cacc.y * sn;
            acc.z = acc.z * so + cacc.z * sn;
            acc.w = acc.w * so + cacc.w * sn;
        }
        float inv = 1.f / den;
        total.x += acc.x * inv;
        total.y += acc.y * inv;
        total.z += acc.z * inv;
        total.w += acc.w * inv;
    }

    if (MEAN) {
        #pragma unroll
        for (int o = 8; o <= 16; o <<= 1) {
            total.x += __shfl_xor_sync(0xFFFFFFFFu, total.x, o);
            total.y += __shfl_xor_sync(0xFFFFFFFFu, total.y, o);
            total.z += __shfl_xor_sync(0xFFFFFFFFu, total.z, o);
            total.w += __shfl_xor_sync(0xFFFFFFFFu, total.w, o);
        }
        if (lane < 8) {
            float4 v = make_float4(0.25f * total.x, 0.25f * total.y,
                                   0.25f * total.z, 0.25f * total.w);
            *(float4*)(out_f + (size_t)dst * DD + lane * 4) = v;
        }
    } else {
        // fp16 hi/lo split write (lo scaled by 2048) for the next GEMM
        __half h0, h1, h2, h3, l0, l1, l2, l3;
        split_h(total.x, h0, l0); split_h(total.y, h1, l1);
        split_h(total.z, h2, l2); split_h(total.w, h3, l3);
        size_t o2 = ((size_t)dst * CC + dbase) >> 1;
        ((__half2*)out_hi)[o2]     = __halves2half2(h0, h1);
        ((__half2*)out_hi)[o2 + 1] = __halves2half2(h2, h3);
        ((__half2*)out_lo)[o2]     = __halves2half2(l0, l1);
        ((__half2*)out_lo)[o2 + 1] = __halves2half2(l2, l3);
    }
}

// ---------------------------------------------------------------------------
// Launch
// ---------------------------------------------------------------------------
extern "C" void kernel_launch(void* const* d_in, const int* in_sizes, int n_in,
                              void* d_out, int out_size) {
    const float* x    = (const float*)d_in[0];
    const int*   esrc = (const int*)d_in[1];
    const int*   edst = (const int*)d_in[2];
    const float* Wsrc[3], *bsrc[3], *Wdst[3], *bdst[3], *attn[3];
    for (int l = 0; l < 3; l++) {
        Wsrc[l] = (const float*)d_in[3 + 5 * l + 0];
        bsrc[l] = (const float*)d_in[3 + 5 * l + 1];
        Wdst[l] = (const float*)d_in[3 + 5 * l + 2];
        bdst[l] = (const float*)d_in[3 + 5 * l + 3];
        attn[l] = (const float*)d_in[3 + 5 * l + 4];
    }

    void *p_fsh, *p_fdh, *p_cnt, *p_off, *p_src;
    void *p_ahi, *p_alo, *p_whi, *p_wlo, *p_bias;
    cudaGetSymbolAddress(&p_fsh, g_fsh);
    cudaGetSymbolAddress(&p_fdh, g_fdh);
    cudaGetSymbolAddress(&p_cnt, g_cnt);
    cudaGetSymbolAddress(&p_off, g_off);
    cudaGetSymbolAddress(&p_src, g_src);
    cudaGetSymbolAddress(&p_ahi, g_ahi);
    cudaGetSymbolAddress(&p_alo, g_alo);
    cudaGetSymbolAddress(&p_whi, g_whi);
    cudaGetSymbolAddress(&p_wlo, g_wlo);
    cudaGetSymbolAddress(&p_bias, g_bias);
    __half* fsh = (__half*)p_fsh;  __half* fdh = (__half*)p_fdh;
    int* cnt = (int*)p_cnt;  int* off = (int*)p_off;  int* csr_src = (int*)p_src;
    __half* ahi = (__half*)p_ahi;  __half* alo = (__half*)p_alo;
    __half* whi = (__half*)p_whi;  __half* wlo = (__half*)p_wlo;
    float* bias = (float*)p_bias;

    static int smem_set = 0;
    if (!smem_set) {
        cudaFuncSetAttribute(k_gemm_mma512,
                             cudaFuncAttributeMaxDynamicSharedMemorySize, GEMM_SMEM3);
        smem_set = 1;
    }

    const int GEMM_MT = (NN + 127) / 128;            // 391
    const int EDGE_BLOCKS = (NN * 32 + 255) / 256;
    const int XCVT_BLOCKS = (NN * CC / 4 + 255) / 256;

    WParams wp;
    for (int l = 0; l < 3; l++) {
        wp.W[2 * l]      = Wsrc[l];  wp.bv[2 * l]      = bsrc[l];
        wp.W[2 * l + 1]  = Wdst[l];  wp.bv[2 * l + 1]  = bdst[l];
    }
    // (1) weights, (2) input split, (3) csr zero, (4) layer-0 GEMM <- profiled
    k_cvt_w_all<<<(6 * RR * CC * CC + 255) / 256, 256>>>(wp, whi, wlo, bias);
    k_cvt_x<<<XCVT_BLOCKS, 256>>>(x, ahi, alo);
    k_zero_cnt<<<(RR * NN + 255) / 256, 256>>>(cnt);
    k_gemm_mma512<<<dim3(GEMM_MT, 8), 512, GEMM_SMEM3>>>(
        ahi, alo, whi, wlo, bias, fsh, fdh);
    // CSR build (scan also writes fill cursors)
    k_count<<<(RR * EE + 255) / 256, 256>>>(edst, cnt);
    k_scan<<<RR, 1024>>>(cnt, off);
    k_fill<<<(RR * EE + 255) / 256, 256>>>(esrc, edst, cnt, csr_src);

    k_edge_agg5<false><<<EDGE_BLOCKS, 256>>>(fsh, fdh, attn[0], off, csr_src,
                                             ahi, alo, nullptr);
    k_gemm_mma512<<<dim3(GEMM_MT, 8), 512, GEMM_SMEM3>>>(
        ahi, alo, whi + (size_t)8 * CC * CC, wlo + (size_t)8 * CC * CC,
        bias + 8 * CC, fsh, fdh);
    k_edge_agg5<false><<<EDGE_BLOCKS, 256>>>(fsh, fdh, attn[1], off, csr_src,
                                             ahi, alo, nullptr);
    k_gemm_mma512<<<dim3(GEMM_MT, 8), 512, GEMM_SMEM3>>>(
        ahi, alo, whi + (size_t)16 * CC * CC, wlo + (size_t)16 * CC * CC,
        bias + 16 * CC, fsh, fdh);
    k_edge_agg5<true><<<EDGE_BLOCKS, 256>>>(fsh, fdh, attn[2], off, csr_src,
                                            nullptr, nullptr, (float*)d_out);
}

// round 15
// speedup vs baseline: 1.3423x; 1.3423x over previous
#include <cuda_runtime.h>
#include <cuda_bf16.h>
#include <cuda_fp16.h>
#include <math_constants.h>
#include <cstdint>

// Problem constants
#define NN   50000
#define EE   200000
#define RR   4
#define CC   128
#define HH   4
#define DD   32

#define LO_SCALE     2048.0f
#define INV_LO_SCALE (1.0f / 2048.0f)

// ---------------------------------------------------------------------------
// Device scratch (allocation-free rule: __device__ globals)
// ---------------------------------------------------------------------------
__device__ __half g_fsh[RR * NN * CC];   // fp16 fs
__device__ __half g_fdh[RR * NN * CC];   // fp16 fd
__device__ int    g_cnt[RR * NN];
__device__ int    g_off[RR * (NN + 1)];
__device__ int    g_src[RR * EE];
__device__ __half g_ah[NN * CC];         // fp16 GEMM input A (features)
__device__ __half g_whi[3 * 8 * CC * CC];   // [layer][block(8)][n][k]
__device__ __half g_wlo[3 * 8 * CC * CC];   // lo pre-scaled by 2048
__device__ float  g_bias[3 * 8 * CC];

// ---------------------------------------------------------------------------
// CSR construction
// ---------------------------------------------------------------------------
__global__ void k_zero_cnt(int* cnt) {
    int i = blockIdx.x * blockDim.x + threadIdx.x;
    if (i < RR * NN) cnt[i] = 0;
}
__global__ void k_count(const int* __restrict__ edst, int* cnt) {
    int i = blockIdx.x * blockDim.x + threadIdx.x;
    if (i >= RR * EE) return;
    int r = i / EE;
    atomicAdd(&cnt[r * NN + edst[i]], 1);
}
// scan counts -> offsets; ALSO writes fill cursors (cnt becomes cursor array)
__global__ void k_scan(int* cnt, int* off) {
    int r = blockIdx.x;
    int t = threadIdx.x;
    const int CH = (NN + 1023) / 1024;
    __shared__ int sums[1024];
    int base = t * CH, s = 0;
    for (int i = 0; i < CH; i++) { int idx = base + i; if (idx < NN) s += cnt[r * NN + idx]; }
    sums[t] = s;
    __syncthreads();
    for (int o = 1; o < 1024; o <<= 1) {
        int v = (t >= o) ? sums[t - o] : 0;
        __syncthreads();
        sums[t] += v;
        __syncthreads();
    }
    int run = (t == 0) ? 0 : sums[t - 1];
    for (int i = 0; i < CH; i++) {
        int idx = base + i;
        if (idx < NN) {
            int c = cnt[r * NN + idx];
            off[r * (NN + 1) + idx] = run;
            cnt[r * NN + idx] = run;     // cursor for k_fill
            run += c;
        }
    }
    if (t == 1023) off[r * (NN + 1) + NN] = run;
}
__global__ void k_fill(const int* __restrict__ esrc, const int* __restrict__ edst,
                       int* cur, int* csr_src) {
    int i = blockIdx.x * blockDim.x + threadIdx.x;
    if (i >= RR * EE) return;
    int r = i / EE;
    int pos = atomicAdd(&cur[r * NN + edst[i]], 1);
    csr_src[r * EE + pos] = esrc[i];
}

// ---------------------------------------------------------------------------
// Conversions
// ---------------------------------------------------------------------------
__global__ void k_cvt_x(const float* __restrict__ x, __half* __restrict__ hi) {
    int i = blockIdx.x * blockDim.x + threadIdx.x;
    if (i >= NN * CC / 4) return;
    float4 v = ((const float4*)x)[i];
    ((__half2*)hi)[2 * i]     = __floats2half2_rn(v.x, v.y);
    ((__half2*)hi)[2 * i + 1] = __floats2half2_rn(v.z, v.w);
}

// Fused weight conversion for all 3 layers x {src,dst}: transpose + hi/lo split
struct WParams {
    const float* W[6];    // Wsrc0, Wdst0, Wsrc1, Wdst1, Wsrc2, Wdst2
    const float* bv[6];
};
__global__ void k_cvt_w_all(WParams p,
                            __half* __restrict__ w_hi, __half* __restrict__ w_lo,
                            float* __restrict__ bias_out) {
    int i = blockIdx.x * blockDim.x + threadIdx.x;
    if (i >= 6 * RR * CC * CC) return;
    int s    = i / (RR * CC * CC);
    int rem  = i - s * (RR * CC * CC);
    int r    = rem / (CC * CC);
    int rem2 = rem - r * (CC * CC);
    int n    = rem2 / CC;
    int k    = rem2 - n * CC;
    int l = s >> 1, ty = s & 1;
    int blk = l * 8 + ty * 4 + r;
    float w = p.W[s][(size_t)r * CC * CC + (size_t)k * CC + n];
    __half h = __float2half_rn(w);
    __half lo = __float2half_rn((w - __half2float(h)) * LO_SCALE);
    size_t oidx = (size_t)blk * CC * CC + (size_t)n * CC + k;
    w_hi[oidx] = h;
    w_lo[oidx] = lo;
    if (k == 0) bias_out[blk * CC + n] = p.bv[s][r * CC + n];
}

// ---------------------------------------------------------------------------
// HMMA helpers
// ---------------------------------------------------------------------------
__device__ __forceinline__ uint32_t smem_u32(const void* p) {
    uint32_t a;
    asm("{ .reg .u64 t; cvta.to.shared.u64 t, %1; cvt.u32.u64 %0, t; }"
        : "=r"(a) : "l"(p));
    return a;
}
__device__ __forceinline__ void ldsm_x4(uint32_t* r, uint32_t addr) {
    asm volatile("ldmatrix.sync.aligned.m8n8.x4.shared.b16 {%0,%1,%2,%3}, [%4];"
        : "=r"(r[0]), "=r"(r[1]), "=r"(r[2]), "=r"(r[3]) : "r"(addr));
}
#define MMA16816F(c, a, b) \
    asm volatile("mma.sync.aligned.m16n8k16.row.col.f32.f16.f16.f32 " \
        "{%0,%1,%2,%3}, {%4,%5,%6,%7}, {%8,%9}, {%0,%1,%2,%3};" \
        : "+f"((c)[0]), "+f"((c)[1]), "+f"((c)[2]), "+f"((c)[3]) \
        : "r"((a)[0]), "r"((a)[1]), "r"((a)[2]), "r"((a)[3]), \
          "r"((b)[0]), "r"((b)[1]))

__device__ __forceinline__ void cp_async16(uint32_t saddr, const void* gptr, bool pred) {
    int sz = pred ? 16 : 0;   // src-size 0 => zero-fill destination
    asm volatile("cp.async.cg.shared.global [%0], [%1], 16, %2;"
        :: "r"(saddr), "l"(gptr), "r"(sz));
}
#define CP_COMMIT() asm volatile("cp.async.commit_group;" ::: "memory")

// K chunked 2 x 64; padded row stride 72 elems -> ldmatrix conflict-free.
#define KCH3   64
#define TP3    72
#define TILE3  (128 * TP3)
#define STAGE3 (3 * TILE3)            // A, Bhi, Blo
#define GEMM_SMEM3 (2 * STAGE3 * 2)   // 110592 B -> 2 CTAs/SM

// ---------------------------------------------------------------------------
// 2-term fp16 GEMM via mma.sync — 512 threads, warp tile 32x32.
// C = A@Bhi + (A@Blo')/2048, both fp32 accumulate. A is plain fp16 (its
// rounding error matches the fp16 feature storage the net already carries).
// grid = (391 M-tiles, 8 N-blocks). b<4 -> fs[r=b], else fd[r=b-4].
// ---------------------------------------------------------------------------
__global__ __launch_bounds__(512) void k_gemm_mma512(
    const __half* __restrict__ a_h,
    const __half* __restrict__ w_hi, const __half* __restrict__ w_lo,
    const float* __restrict__ bias,
    __half* __restrict__ fs, __half* __restrict__ fd) {
    extern __shared__ __align__(16) char dsm[];
    __half* smem = (__half*)dsm;

    const int tid  = threadIdx.x;
    const int wid  = tid >> 5;
    const int lane = tid & 31;
    const int wm   = wid >> 2;
    const int wn   = wid & 3;
    const int m0   = blockIdx.x * 128;
    const int b    = blockIdx.y;

    const __half* srcs[3] = {
        a_h + (size_t)m0 * CC,
        w_hi + (size_t)b * CC * CC,
        w_lo + (size_t)b * CC * CC };

    // 6 cp.async x 16B per thread per stage (3 tiles x 128 rows x 8 chunks)
    auto prefetch = [&](int c, int s) {
        int k0 = c * KCH3;
        __half* st = smem + s * STAGE3;
        #pragma unroll
        for (int i = 0; i < 6; i++) {
            int idx = tid + i * 512;
            int t   = idx >> 10;
            int w   = idx & 1023;
            int row = w >> 3, ch = w & 7;
            const __half* gp = srcs[t] + (size_t)row * CC + k0 + ch * 8;
            uint32_t sa = smem_u32(st + t * TILE3 + row * TP3 + ch * 8);
            bool ok = (t >= 1) || ((m0 + row) < NN);
            cp_async16(sa, gp, ok);
        }
        CP_COMMIT();
    };

    float acc[2][4][4];    // A@Bhi
    float acc2[2][4][4];   // A@Blo (scaled)
    #pragma unroll
    for (int i = 0; i < 2; i++)
        #pragma unroll
        for (int j = 0; j < 4; j++)
            #pragma unroll
            for (int q = 0; q < 4; q++) { acc[i][j][q] = 0.f; acc2[i][j][q] = 0.f; }

    const int sub = lane >> 3;
    const int rin = lane & 7;

    prefetch(0, 0);
    prefetch(1, 1);

    #pragma unroll
    for (int c = 0; c < 2; c++) {
        if (c == 0) asm volatile("cp.async.wait_group 1;" ::: "memory");
        else        asm volatile("cp.async.wait_group 0;" ::: "memory");
        __syncthreads();

        __half* sA   = smem + c * STAGE3;
        __half* sBhi = sA + TILE3;
        __half* sBlo = sBhi + TILE3;

        #pragma unroll
        for (int kk = 0; kk < KCH3; kk += 16) {
            uint32_t af[2][4], bfh[4][2], bfl[4][2];
            #pragma unroll
            for (int mt = 0; mt < 2; mt++) {
                int ar = wm * 32 + mt * 16 + (sub & 1) * 8 + rin;
                int ac = kk + (sub >> 1) * 8;
                ldsm_x4(af[mt], smem_u32(sA + ar * TP3 + ac));
            }
            #pragma unroll
            for (int nt2 = 0; nt2 < 2; nt2++) {
                int br = wn * 32 + nt2 * 16 + (sub >> 1) * 8 + rin;
                int bc = kk + (sub & 1) * 8;
                int off = br * TP3 + bc;
                uint32_t t[4];
                ldsm_x4(t, smem_u32(sBhi + off));
                bfh[nt2 * 2][0] = t[0]; bfh[nt2 * 2][1] = t[1];
                bfh[nt2 * 2 + 1][0] = t[2]; bfh[nt2 * 2 + 1][1] = t[3];
                ldsm_x4(t, smem_u32(sBlo + off));
                bfl[nt2 * 2][0] = t[0]; bfl[nt2 * 2][1] = t[1];
                bfl[nt2 * 2 + 1][0] = t[2]; bfl[nt2 * 2 + 1][1] = t[3];
            }
            #pragma unroll
            for (int mt = 0; mt < 2; mt++)
                #pragma unroll
                for (int nt = 0; nt < 4; nt++) {
                    MMA16816F(acc[mt][nt],  af[mt], bfh[nt]);
                    MMA16816F(acc2[mt][nt], af[mt], bfl[nt]);
                }
        }
    }

    __half* outp = (b < 4) ? (fs + (size_t)b * NN * CC)
                           : (fd + (size_t)(b - 4) * NN * CC);
    const float* bv = bias + b * CC;
    const int qr = lane >> 2, qc = lane & 3;
    #pragma unroll
    for (int mt = 0; mt < 2; mt++) {
        int mA = m0 + wm * 32 + mt * 16 + qr;
        #pragma unroll
        for (int nt = 0; nt < 4; nt++) {
            int n = wn * 32 + nt * 8 + qc * 2;
            float b0 = bv[n], b1 = bv[n + 1];
            if (mA < NN) {
                __half2 v0 = __floats2half2_rn(
                    acc[mt][nt][0] + acc2[mt][nt][0] * INV_LO_SCALE + b0,
                    acc[mt][nt][1] + acc2[mt][nt][1] * INV_LO_SCALE + b1);
                *(__half2*)(outp + (size_t)mA * CC + n) = v0;
            }
            if (mA + 8 < NN) {
                __half2 v1 = __floats2half2_rn(
                    acc[mt][nt][2] + acc2[mt][nt][2] * INV_LO_SCALE + b0,
                    acc[mt][nt][3] + acc2[mt][nt][3] * INV_LO_SCALE + b1);
                *(__half2*)(outp + (size_t)(mA + 8) * CC + n) = v1;
            }
        }
    }
}

// ---------------------------------------------------------------------------
// Edge aggregation v4 (R12 version — best known): one warp per dst,
// 4 heads in 8-lane groups, single-state online softmax, 1-deep prefetch.
// Non-MEAN writes plain fp16 features (= next GEMM's A).
// ---------------------------------------------------------------------------
__device__ __forceinline__ float4 h4_to_f4(uint2 raw) {
    __half2 a = *reinterpret_cast<__half2*>(&raw.x);
    __half2 b = *reinterpret_cast<__half2*>(&raw.y);
    float2 fa = __half22float2(a), fb = __half22float2(b);
    return make_float4(fa.x, fa.y, fb.x, fb.y);
}

template <bool MEAN>
__global__ __launch_bounds__(256) void k_edge_agg4(
    const __half* __restrict__ fs, const __half* __restrict__ fd,
    const float* __restrict__ attn,
    const int* __restrict__ off, const int* __restrict__ csr_src,
    __half* __restrict__ out_h, float* __restrict__ out_f) {
    int dst  = (blockIdx.x * blockDim.x + threadIdx.x) >> 5;
    int lane = threadIdx.x & 31;
    if (dst >= NN) return;
    const int dbase = (lane >> 3) * DD + (lane & 7) * 4;

    float4 total = make_float4(0.f, 0.f, 0.f, 0.f);
    #pragma unroll
    for (int r = 0; r < RR; r++) {
        const __half* fsr = fs + (size_t)r * NN * CC;
        float4 fdv = h4_to_f4(*(const uint2*)(fd + (size_t)r * NN * CC
                                              + (size_t)dst * CC + dbase));
        float4 av  = *(const float4*)(attn + r * HH * DD + dbase);
        int beg = off[r * (NN + 1) + dst];
        int end = off[r * (NN + 1) + dst + 1];

        float m = -CUDART_INF_F, den = 0.f;
        float4 acc = make_float4(0.f, 0.f, 0.f, 0.f);
        if (beg < end) {
            const int* sp = csr_src + r * EE;
            uint2 rnext = *(const uint2*)(fsr + (size_t)sp[beg] * CC + dbase);
            for (int e = beg; e < end; e++) {
                uint2 raw = rnext;
                if (e + 1 < end)
                    rnext = *(const uint2*)(fsr + (size_t)sp[e + 1] * CC + dbase);
                float4 f = h4_to_f4(raw);
                float x0 = f.x + fdv.x, x1 = f.y + fdv.y;
                float x2 = f.z + fdv.z, x3 = f.w + fdv.w;
                x0 = (x0 > 0.f) ? x0 : 0.2f * x0;
                x1 = (x1 > 0.f) ? x1 : 0.2f * x1;
                x2 = (x2 > 0.f) ? x2 : 0.2f * x2;
                x3 = (x3 > 0.f) ? x3 : 0.2f * x3;
                float p = x0 * av.x + x1 * av.y + x2 * av.z + x3 * av.w;
                p += __shfl_xor_sync(0xFFFFFFFFu, p, 1);
                p += __shfl_xor_sync(0xFFFFFFFFu, p, 2);
                p += __shfl_xor_sync(0xFFFFFFFFu, p, 4);
                float nm = fmaxf(m, p);
                float c  = __expf(m - nm);
                float w  = __expf(p - nm);
                m = nm;
                den = den * c + w;
                acc.x = acc.x * c + w * f.x;
                acc.y = acc.y * c + w * f.y;
                acc.z = acc.z * c + w * f.z;
                acc.w = acc.w * c + w * f.w;
            }
            float inv = 1.f / den;
            total.x += acc.x * inv;
            total.y += acc.y * inv;
            total.z += acc.z * inv;
            total.w += acc.w * inv;
        }
    }

    if (MEAN) {
        #pragma unroll
        for (int o = 8; o <= 16; o <<= 1) {
            total.x += __shfl_xor_sync(0xFFFFFFFFu, total.x, o);
            total.y += __shfl_xor_sync(0xFFFFFFFFu, total.y, o);
            total.z += __shfl_xor_sync(0xFFFFFFFFu, total.z, o);
            total.w += __shfl_xor_sync(0xFFFFFFFFu, total.w, o);
        }
        if (lane < 8) {
            float4 v = make_float4(0.25f * total.x, 0.25f * total.y,
                                   0.25f * total.z, 0.25f * total.w);
            *(float4*)(out_f + (size_t)dst * DD + lane * 4) = v;
        }
    } else {
        size_t o2 = ((size_t)dst * CC + dbase) >> 1;
        ((__half2*)out_h)[o2]     = __floats2half2_rn(total.x, total.y);
        ((__half2*)out_h)[o2 + 1] = __floats2half2_rn(total.z, total.w);
    }
}

// ---------------------------------------------------------------------------
// Launch
// ---------------------------------------------------------------------------
extern "C" void kernel_launch(void* const* d_in, const int* in_sizes, int n_in,
                              void* d_out, int out_size) {
    const float* x    = (const float*)d_in[0];
    const int*   esrc = (const int*)d_in[1];
    const int*   edst = (const int*)d_in[2];
    const float* Wsrc[3], *bsrc[3], *Wdst[3], *bdst[3], *attn[3];
    for (int l = 0; l < 3; l++) {
        Wsrc[l] = (const float*)d_in[3 + 5 * l + 0];
        bsrc[l] = (const float*)d_in[3 + 5 * l + 1];
        Wdst[l] = (const float*)d_in[3 + 5 * l + 2];
        bdst[l] = (const float*)d_in[3 + 5 * l + 3];
        attn[l] = (const float*)d_in[3 + 5 * l + 4];
    }

    void *p_fsh, *p_fdh, *p_cnt, *p_off, *p_src;
    void *p_ah, *p_whi, *p_wlo, *p_bias;
    cudaGetSymbolAddress(&p_fsh, g_fsh);
    cudaGetSymbolAddress(&p_fdh, g_fdh);
    cudaGetSymbolAddress(&p_cnt, g_cnt);
    cudaGetSymbolAddress(&p_off, g_off);
    cudaGetSymbolAddress(&p_src, g_src);
    cudaGetSymbolAddress(&p_ah,  g_ah);
    cudaGetSymbolAddress(&p_whi, g_whi);
    cudaGetSymbolAddress(&p_wlo, g_wlo);
    cudaGetSymbolAddress(&p_bias, g_bias);
    __half* fsh = (__half*)p_fsh;  __half* fdh = (__half*)p_fdh;
    int* cnt = (int*)p_cnt;  int* off = (int*)p_off;  int* csr_src = (int*)p_src;
    __half* ah  = (__half*)p_ah;
    __half* whi = (__half*)p_whi;  __half* wlo = (__half*)p_wlo;
    float* bias = (float*)p_bias;

    static int smem_set = 0;
    if (!smem_set) {
        cudaFuncSetAttribute(k_gemm_mma512,
                             cudaFuncAttributeMaxDynamicSharedMemorySize, GEMM_SMEM3);
        smem_set = 1;
    }

    const int GEMM_MT = (NN + 127) / 128;            // 391
    const int EDGE_BLOCKS = (NN * 32 + 255) / 256;
    const int XCVT_BLOCKS = (NN * CC / 4 + 255) / 256;

    WParams wp;
    for (int l = 0; l < 3; l++) {
        wp.W[2 * l]      = Wsrc[l];  wp.bv[2 * l]      = bsrc[l];
        wp.W[2 * l + 1]  = Wdst[l];  wp.bv[2 * l + 1]  = bdst[l];
    }
    // (1) weights, (2) input cvt, (3) csr zero, (4) layer-0 GEMM <- profiled
    k_cvt_w_all<<<(6 * RR * CC * CC + 255) / 256, 256>>>(wp, whi, wlo, bias);
    k_cvt_x<<<XCVT_BLOCKS, 256>>>(x, ah);
    k_zero_cnt<<<(RR * NN + 255) / 256, 256>>>(cnt);
    k_gemm_mma512<<<dim3(GEMM_MT, 8), 512, GEMM_SMEM3>>>(
        ah, whi, wlo, bias, fsh, fdh);
    // CSR build (scan also writes fill cursors)
    k_count<<<(RR * EE + 255) / 256, 256>>>(edst, cnt);
    k_scan<<<RR, 1024>>>(cnt, off);
    k_fill<<<(RR * EE + 255) / 256, 256>>>(esrc, edst, cnt, csr_src);

    k_edge_agg4<false><<<EDGE_BLOCKS, 256>>>(fsh, fdh, attn[0], off, csr_src,
                                             ah, nullptr);
    k_gemm_mma512<<<dim3(GEMM_MT, 8), 512, GEMM_SMEM3>>>(
        ah, whi + (size_t)8 * CC * CC, wlo + (size_t)8 * CC * CC,
        bias + 8 * CC, fsh, fdh);
    k_edge_agg4<false><<<EDGE_BLOCKS, 256>>>(fsh, fdh, attn[1], off, csr_src,
                                             ah, nullptr);
    k_gemm_mma512<<<dim3(GEMM_MT, 8), 512, GEMM_SMEM3>>>(
        ah, whi + (size_t)16 * CC * CC, wlo + (size_t)16 * CC * CC,
        bias + 16 * CC, fsh, fdh);
    k_edge_agg4<true><<<EDGE_BLOCKS, 256>>>(fsh, fdh, attn[2], off, csr_src,
                                            nullptr, (float*)d_out);
}